// round 13
// baseline (speedup 1.0000x reference)
#include <cuda_runtime.h>
#include <cuda_fp16.h>
#include <cstdint>

// ---------------------------------------------------------------------------
// Swin WindowAttention, sm_103 base ISA.
//   GEMMs: fp16 mma.sync m16n8k16, BM=128 BN=128 BK=64, 4 warps each 64x64,
//   3-stage cp.async pipeline.
//   Attention: HMMA per (window,head): QK 1-pass, AV 1-pass; padded-region
//   exps skipped at warp granularity (MUFU-bound kernel).
// ---------------------------------------------------------------------------

#define N_WIN 4096
#define L_TOK 49
#define CH    256
#define NHEAD 8
#define DK    32
#define M_ROWS (N_WIN * L_TOK)   // 200704
#define BMROW 52
#define BMWIN 2560

__device__ __half g_xh[(size_t)M_ROWS * CH];
__device__ __half g_qh[(size_t)M_ROWS * 768];
__device__ __half g_ah[(size_t)M_ROWS * CH];
__device__ __half g_wqkv[256 * 768];
__device__ __half g_wo[256 * 256];
__device__ float  g_bm[512 * BMWIN];

// ------------------------------ helpers ------------------------------------

__device__ __forceinline__ uint32_t smem_u32(const void* p) {
    uint32_t a;
    asm("{ .reg .u64 t; cvta.to.shared.u64 t, %1; cvt.u32.u64 %0, t; }"
        : "=r"(a) : "l"(p));
    return a;
}
__device__ __forceinline__ void cp16(uint32_t dst, const void* src) {
    asm volatile("cp.async.cg.shared.global [%0], [%1], 16;"
                 :: "r"(dst), "l"(src));
}
#define CP_COMMIT() asm volatile("cp.async.commit_group;" ::: "memory")
#define CP_WAIT2()  asm volatile("cp.async.wait_group 2;" ::: "memory")
#define CP_WAIT1()  asm volatile("cp.async.wait_group 1;" ::: "memory")
#define CP_WAIT0()  asm volatile("cp.async.wait_group 0;" ::: "memory")

__device__ __forceinline__ void ldsm_x4(uint32_t addr, uint32_t* r) {
    asm volatile("ldmatrix.sync.aligned.m8n8.x4.shared.b16 {%0,%1,%2,%3}, [%4];"
                 : "=r"(r[0]), "=r"(r[1]), "=r"(r[2]), "=r"(r[3]) : "r"(addr));
}
__device__ __forceinline__ void ldsm_x4_t(uint32_t addr, uint32_t* r) {
    asm volatile("ldmatrix.sync.aligned.m8n8.x4.trans.shared.b16 {%0,%1,%2,%3}, [%4];"
                 : "=r"(r[0]), "=r"(r[1]), "=r"(r[2]), "=r"(r[3]) : "r"(addr));
}
__device__ __forceinline__ void mma16816(float* c, const uint32_t* a,
                                         const uint32_t* b) {
    asm volatile(
        "mma.sync.aligned.m16n8k16.row.col.f32.f16.f16.f32 "
        "{%0,%1,%2,%3}, {%4,%5,%6,%7}, {%8,%9}, {%0,%1,%2,%3};"
        : "+f"(c[0]), "+f"(c[1]), "+f"(c[2]), "+f"(c[3])
        : "r"(a[0]), "r"(a[1]), "r"(a[2]), "r"(a[3]), "r"(b[0]), "r"(b[1]));
}
__device__ __forceinline__ uint32_t pack_h2(float x, float y) {
    __half2 v = __halves2half2(__float2half_rn(x), __float2half_rn(y));
    return *(uint32_t*)&v;
}

// ------------------------------ prep kernels --------------------------------

__global__ void k_split_x(const float* __restrict__ x) {
    int i = blockIdx.x * blockDim.x + threadIdx.x;
    if (i >= (M_ROWS * CH) / 4) return;
    float4 v = ((const float4*)x)[i];
    ((__half2*)g_xh)[i * 2] =
        __halves2half2(__float2half_rn(v.x), __float2half_rn(v.y));
    ((__half2*)g_xh)[i * 2 + 1] =
        __halves2half2(__float2half_rn(v.z), __float2half_rn(v.w));
}

__global__ void k_split_w(const float* __restrict__ wq,
                          const float* __restrict__ wk,
                          const float* __restrict__ wv,
                          const float* __restrict__ wo) {
    int gid = blockIdx.x * blockDim.x + threadIdx.x;
    if (gid >= 65536) return;
    int sect = gid >> 14;
    int i    = gid & 16383;
    const float* src = (sect == 0) ? wq : (sect == 1) ? wk
                     : (sect == 2) ? wv : wo;
    float4 v = ((const float4*)src)[i];
    __half2 a = __halves2half2(__float2half_rn(v.x), __float2half_rn(v.y));
    __half2 b = __halves2half2(__float2half_rn(v.z), __float2half_rn(v.w));
    int k = (i * 4) >> 8;
    int n = (i * 4) & 255;
    if (sect < 3) {
        __half2* d = (__half2*)&g_wqkv[(size_t)k * 768 + sect * 256 + n];
        d[0] = a; d[1] = b;
    } else {
        __half2* d = (__half2*)&g_wo[(size_t)k * 256 + n];
        d[0] = a; d[1] = b;
    }
}

__global__ void k_bm(const float* __restrict__ mask,
                     const float* __restrict__ bias_table,
                     const int* __restrict__ rel_index) {
    const int bid = blockIdx.x;
    const int w   = bid >> 3;
    const int h   = bid & 7;
    float* dst = g_bm + (size_t)bid * BMWIN;
    const float* mrow = mask + (size_t)w * (L_TOK * L_TOK);
    for (int i = threadIdx.x; i < L_TOK * L_TOK; i += blockDim.x)
        dst[(i / L_TOK) * BMROW + (i % L_TOK)] =
            bias_table[rel_index[i] * NHEAD + h] + mrow[i];
}

// ------------------------------ GEMM ----------------------------------------
// BM=128 BN=128 BK=64, 4 warps (2m x 2n), warp tile 64x64, 3-stage cp.async.

#define AROWH 72
#define BROWH 136
#define O_A 0
#define O_B 18432
#define S_BUF 35840
#define SMEM_BYTES (3 * S_BUF)   // 107520; 2 CTAs/SM = 215040 <= 228K
#define CS 136

__global__ __launch_bounds__(128, 2)
void k_hgemm(const __half* __restrict__ Ah, const __half* __restrict__ Wh,
             int ldW, float* __restrict__ Cf, int ldC, int mode)
{
    extern __shared__ char smem[];
    const uint32_t sb = smem_u32(smem);
    const int tid  = threadIdx.x;
    const int lane = tid & 31;
    const int wid  = tid >> 5;
    const int warp_m = wid & 1;
    const int warp_n = wid >> 1;
    const int rowBlock = blockIdx.y * 128;
    const int col0     = blockIdx.x * 128;

    float acc[4][8][4];
#pragma unroll
    for (int mt = 0; mt < 4; mt++)
#pragma unroll
        for (int nt = 0; nt < 8; nt++)
#pragma unroll
            for (int i = 0; i < 4; i++) acc[mt][nt][i] = 0.f;

    auto issue = [&](int c, int buf) {
        uint32_t s = sb + buf * S_BUF;
#pragma unroll
        for (int q8 = 0; q8 < 8; q8++) {
            int q   = tid + 128 * q8;
            int row = q >> 3;
            int seg = (q & 7) * 8;
            cp16(s + O_A + row * (AROWH * 2) + seg * 2,
                 Ah + (size_t)(rowBlock + row) * CH + c * 64 + seg);
        }
#pragma unroll
        for (int q8 = 0; q8 < 8; q8++) {
            int q   = tid + 128 * q8;
            int k   = q >> 4;
            int seg = (q & 15) * 8;
            cp16(s + O_B + k * (BROWH * 2) + seg * 2,
                 Wh + (size_t)(c * 64 + k) * ldW + col0 + seg);
        }
        CP_COMMIT();
    };

    const int arow_l = warp_m * 64 + (lane & 15);
    const int acol_l = (lane >> 4) * 8;
    const int brow_l = (lane & 7) + ((lane >> 3) & 1) * 8;
    const int bcol_l = warp_n * 64 + (lane >> 4) * 8;

    issue(0, 0);
    issue(1, 1);

#pragma unroll 1
    for (int c = 0; c < 4; c++) {
        if (c < 2) issue(c + 2, (c + 2 == 2) ? 2 : 0);   // (c+2)%3
        if (c <= 1)      CP_WAIT2();
        else if (c == 2) CP_WAIT1();
        else             CP_WAIT0();
        __syncthreads();

        const uint32_t s = sb + (uint32_t)(c % 3) * S_BUF;
#pragma unroll
        for (int ks = 0; ks < 4; ks++) {
            uint32_t a[4][4], b[4][4];
            const uint32_t aoff = (acol_l + ks * 16) * 2;
#pragma unroll
            for (int mt = 0; mt < 4; mt++)
                ldsm_x4(s + O_A + (arow_l + mt * 16) * (AROWH * 2) + aoff,
                        a[mt]);
            const uint32_t brow = (brow_l + ks * 16) * (BROWH * 2);
#pragma unroll
            for (int np = 0; np < 4; np++)
                ldsm_x4_t(s + O_B + brow + (bcol_l + np * 16) * 2, b[np]);
#pragma unroll
            for (int mt = 0; mt < 4; mt++)
#pragma unroll
                for (int nt = 0; nt < 8; nt++)
                    mma16816(acc[mt][nt], a[mt], &b[nt >> 1][(nt & 1) * 2]);
        }
        __syncthreads();
    }

    // ---- epilogue via smem -> STG.128 ----
    float* cs = (float*)smem;
    const int g  = lane >> 2;
    const int tc = (lane & 3) * 2;
#pragma unroll
    for (int mt = 0; mt < 4; mt++) {
        const int r = warp_m * 64 + mt * 16 + g;
#pragma unroll
        for (int nt = 0; nt < 8; nt++) {
            const int cc = warp_n * 64 + nt * 8 + tc;
            *(float2*)&cs[r * CS + cc] =
                make_float2(acc[mt][nt][0], acc[mt][nt][1]);
            *(float2*)&cs[(r + 8) * CS + cc] =
                make_float2(acc[mt][nt][2], acc[mt][nt][3]);
        }
    }
    __syncthreads();

#pragma unroll
    for (int i = 0; i < 16; i++) {
        const int id  = tid + 128 * i;
        const int row = id >> 4;
        const int col = (id & 15) * 8;
        float4 v0 = *(float4*)&cs[row * CS + col];
        float4 v1 = *(float4*)&cs[row * CS + col + 4];
        if (mode == 0) {
            uint4 hi;
            hi.x = pack_h2(v0.x, v0.y); hi.y = pack_h2(v0.z, v0.w);
            hi.z = pack_h2(v1.x, v1.y); hi.w = pack_h2(v1.z, v1.w);
            size_t o = (size_t)(rowBlock + row) * 768 + col0 + col;
            *(uint4*)&g_qh[o] = hi;
        } else {
            size_t o = (size_t)(rowBlock + row) * ldC + col0 + col;
            *(float4*)&Cf[o]     = v0;
            *(float4*)&Cf[o + 4] = v1;
        }
    }
}

// ------------------------------ attention (HMMA) ----------------------------
// One CTA per (window, head), 4 warps. QK 1-pass, AV 1-pass.
// Padded-score exps skipped: nt=7 column tile zeroed without exp; warp 3
// skips all row-1 softmax work (rows 56..63 are never stored).

#define KSTR 40

__global__ __launch_bounds__(128)
void attn_kernel()
{
    __shared__ __align__(16) __half sQ [64 * KSTR];
    __shared__ __align__(16) __half sKh[64 * KSTR];
    __shared__ __align__(16) __half sVh[64 * KSTR];

    const int bid = blockIdx.x;
    const int h   = bid & 7;
    const int n   = bid >> 3;
    const int tid = threadIdx.x;

    for (int idx = tid; idx < 60; idx += 128) {
        int r  = 49 + (idx >> 2);
        int q4 = idx & 3;
        *(int4*)(sVh + r * KSTR + q4 * 8) = make_int4(0, 0, 0, 0);
    }
    {
        const size_t rb = (size_t)n * L_TOK * 768 + h * DK;
        for (int idx = tid; idx < 3 * 196; idx += 128) {
            int p   = idx / 196;
            int rem = idx - p * 196;
            int r   = rem >> 2;
            int q4  = rem & 3;
            const __half* src;
            __half* dst;
            switch (p) {
                case 0: src = g_qh + rb;       dst = sQ;  break;
                case 1: src = g_qh + rb + 256; dst = sKh; break;
                default: src = g_qh + rb + 512; dst = sVh; break;
            }
            *(int4*)(dst + r * KSTR + q4 * 8) =
                *(const int4*)(src + (size_t)r * 768 + q4 * 8);
        }
    }
    __syncthreads();

    const int warp = tid >> 5;
    const int lane = tid & 31;
    const int g    = lane >> 2;
    const int t    = lane & 3;

    const uint32_t bq  = smem_u32(sQ);
    const uint32_t bkh = smem_u32(sKh);
    const int aRow = warp * 16 + (lane & 15);
    const int aCol = (lane >> 4) * 8;

    uint32_t qa[2][4];
    ldsm_x4(bq + (aRow * KSTR + aCol) * 2, qa[0]);
    ldsm_x4(bq + (aRow * KSTR + aCol + 16) * 2, qa[1]);

    float c[8][4];
#pragma unroll
    for (int nt = 0; nt < 8; nt++)
#pragma unroll
        for (int i = 0; i < 4; i++) c[nt][i] = 0.f;

#pragma unroll
    for (int kt = 0; kt < 2; kt++) {
#pragma unroll
        for (int jp = 0; jp < 4; jp++) {
            uint32_t kb[4];
            ldsm_x4(bkh + ((jp * 16 + (lane & 15)) * KSTR +
                           (lane >> 4) * 8 + kt * 16) * 2, kb);
            uint32_t b0[2] = {kb[0], kb[2]};
            uint32_t b1[2] = {kb[1], kb[3]};
            mma16816(c[jp * 2],     qa[kt], b0);
            mma16816(c[jp * 2 + 1], qa[kt], b1);
        }
    }

    // ---- bias+mask from L2, softmax with padded-region skip ----
    const int r0 = warp * 16 + g;               // rows 0..55 (warp3: 48..55)
    const int r1 = r0 + 8;                      // rows 8..63 (warp3: 56..63)
    const float* bm = g_bm + (size_t)(((n & 63) << 3) | h) * BMWIN;
    const int r0e = (r0 < L_TOK ? r0 : L_TOK - 1) * BMROW;

    // row 0 group: valid for all warps (row >= 49 lanes produce unused rows)
#pragma unroll
    for (int nt = 0; nt < 7; nt++) {
        const int j0 = nt * 8 + t * 2;
        if (j0 < L_TOK) {
            float2 b0 = __ldg((const float2*)&bm[r0e + j0]);
            c[nt][0] += b0.x;
            if (j0 + 1 < L_TOK) c[nt][1] += b0.y;
            else                c[nt][1] = -3.0e38f;
        } else {
            c[nt][0] = -3.0e38f; c[nt][1] = -3.0e38f;
        }
    }
    if (warp < 3) {
        const int r1e = r1 * BMROW;             // r1 <= 47 here
#pragma unroll
        for (int nt = 0; nt < 7; nt++) {
            const int j0 = nt * 8 + t * 2;
            if (j0 < L_TOK) {
                float2 b1 = __ldg((const float2*)&bm[r1e + j0]);
                c[nt][2] += b1.x;
                if (j0 + 1 < L_TOK) c[nt][3] += b1.y;
                else                c[nt][3] = -3.0e38f;
            } else {
                c[nt][2] = -3.0e38f; c[nt][3] = -3.0e38f;
            }
        }
    }

    float mx0 = -3.0e38f;
#pragma unroll
    for (int nt = 0; nt < 7; nt++)
        mx0 = fmaxf(mx0, fmaxf(c[nt][0], c[nt][1]));
    mx0 = fmaxf(mx0, __shfl_xor_sync(0xffffffffu, mx0, 1));
    mx0 = fmaxf(mx0, __shfl_xor_sync(0xffffffffu, mx0, 2));

    float s0 = 0.f, s1 = 1.f, rs1 = 1.f;
#pragma unroll
    for (int nt = 0; nt < 7; nt++) {
        c[nt][0] = __expf(c[nt][0] - mx0); s0 += c[nt][0];
        c[nt][1] = __expf(c[nt][1] - mx0); s0 += c[nt][1];
    }
    s0 += __shfl_xor_sync(0xffffffffu, s0, 1);
    s0 += __shfl_xor_sync(0xffffffffu, s0, 2);
    const float rs0 = 1.f / s0;

    if (warp < 3) {
        float mx1 = -3.0e38f;
#pragma unroll
        for (int nt = 0; nt < 7; nt++)
            mx1 = fmaxf(mx1, fmaxf(c[nt][2], c[nt][3]));
        mx1 = fmaxf(mx1, __shfl_xor_sync(0xffffffffu, mx1, 1));
        mx1 = fmaxf(mx1, __shfl_xor_sync(0xffffffffu, mx1, 2));
        s1 = 0.f;
#pragma unroll
        for (int nt = 0; nt < 7; nt++) {
            c[nt][2] = __expf(c[nt][2] - mx1); s1 += c[nt][2];
            c[nt][3] = __expf(c[nt][3] - mx1); s1 += c[nt][3];
        }
        s1 += __shfl_xor_sync(0xffffffffu, s1, 1);
        s1 += __shfl_xor_sync(0xffffffffu, s1, 2);
        rs1 = 1.f / s1;
    }
    // column tile 7 (cols 56..63) is entirely padding: P = 0, no exps.
    c[7][0] = c[7][1] = c[7][2] = c[7][3] = 0.f;

    // ---- AV: single pass ----
    const uint32_t bvh = smem_u32(sVh);
    const int vRow = (lane & 7) + ((lane >> 3) & 1) * 8;
    const int vCol = (lane >> 4) * 8;

    float o[4][4];
#pragma unroll
    for (int nt = 0; nt < 4; nt++)
#pragma unroll
        for (int i = 0; i < 4; i++) o[nt][i] = 0.f;

#pragma unroll
    for (int kt = 0; kt < 4; kt++) {
        uint32_t ph[4];
#pragma unroll
        for (int q = 0; q < 2; q++) {
            const float* cc = c[2 * kt + q];
            ph[q * 2]     = pack_h2(cc[0], cc[1]);
            ph[q * 2 + 1] = pack_h2(cc[2], cc[3]);
        }
        uint32_t vh[2][4];
        const uint32_t roff = (kt * 16 + vRow) * KSTR;
        ldsm_x4_t(bvh + (roff + vCol) * 2,      vh[0]);
        ldsm_x4_t(bvh + (roff + vCol + 16) * 2, vh[1]);
#pragma unroll
        for (int nt = 0; nt < 4; nt++)
            mma16816(o[nt], ph, &vh[nt >> 1][(nt & 1) * 2]);
    }

    if (r0 < L_TOK) {
        __half* orow = g_ah + (size_t)(n * L_TOK + r0) * CH + h * DK;
#pragma unroll
        for (int nt = 0; nt < 4; nt++)
            *(__half2*)&orow[nt * 8 + t * 2] =
                __halves2half2(__float2half_rn(o[nt][0] * rs0),
                               __float2half_rn(o[nt][1] * rs0));
    }
    if (r1 < L_TOK) {
        __half* orow = g_ah + (size_t)(n * L_TOK + r1) * CH + h * DK;
#pragma unroll
        for (int nt = 0; nt < 4; nt++)
            *(__half2*)&orow[nt * 8 + t * 2] =
                __halves2half2(__float2half_rn(o[nt][2] * rs1),
                               __float2half_rn(o[nt][3] * rs1));
    }
}

// ------------------------------- launch --------------------------------------

extern "C" void kernel_launch(void* const* d_in, const int* in_sizes, int n_in,
                              void* d_out, int out_size)
{
    (void)in_sizes; (void)n_in; (void)out_size;
    const float* x    = (const float*)d_in[0];
    const float* mask = (const float*)d_in[1];
    const float* wq   = (const float*)d_in[2];
    const float* wk   = (const float*)d_in[3];
    const float* wv   = (const float*)d_in[4];
    const float* wo   = (const float*)d_in[5];
    const float* bias = (const float*)d_in[6];
    const int*   rel  = (const int*)d_in[7];
    float* out = (float*)d_out;

    static __half *xh = nullptr, *ah = nullptr, *wqkv = nullptr, *woh = nullptr;
    if (!xh) {
        cudaGetSymbolAddress((void**)&xh,   g_xh);
        cudaGetSymbolAddress((void**)&ah,   g_ah);
        cudaGetSymbolAddress((void**)&wqkv, g_wqkv);
        cudaGetSymbolAddress((void**)&woh,  g_wo);
        cudaFuncSetAttribute(k_hgemm,
                             cudaFuncAttributeMaxDynamicSharedMemorySize,
                             SMEM_BYTES);
    }

    k_split_x<<<(M_ROWS * CH / 4 + 255) / 256, 256>>>(x);
    k_split_w<<<256, 256>>>(wq, wk, wv, wo);
    k_bm<<<512, 256>>>(mask, bias, rel);
    k_hgemm<<<dim3(6, M_ROWS / 128), 128, SMEM_BYTES>>>(xh, wqkv, 768,
                                                        nullptr, 768, 0);
    attn_kernel<<<N_WIN * NHEAD, 128>>>();
    k_hgemm<<<dim3(2, M_ROWS / 128), 128, SMEM_BYTES>>>(ah, woh, 256,
                                                        out, 256, 1);
}

// round 14
// speedup vs baseline: 1.1060x; 1.1060x over previous
#include <cuda_runtime.h>
#include <cuda_fp16.h>
#include <cstdint>

// ---------------------------------------------------------------------------
// Swin WindowAttention, sm_103 base ISA.
//   GEMMs: fp16 mma.sync m16n8k16, BM=128 BN=128 BK=64, 4 warps each 64x64,
//   2-stage cp.async pipeline (R12 config).
//   Attention: HMMA per (window,head), QK 1-pass, AV 1-pass, cp.async loads.
//   Prep (x split, w split, bias+mask) merged into one launch.
// ---------------------------------------------------------------------------

#define N_WIN 4096
#define L_TOK 49
#define CH    256
#define NHEAD 8
#define DK    32
#define M_ROWS (N_WIN * L_TOK)   // 200704
#define BMROW 52
#define BMWIN 2560

__device__ __half g_xh[(size_t)M_ROWS * CH];
__device__ __half g_qh[(size_t)M_ROWS * 768];
__device__ __half g_ah[(size_t)M_ROWS * CH];
__device__ __half g_wqkv[256 * 768];
__device__ __half g_wo[256 * 256];
__device__ float  g_bm[512 * BMWIN];

// ------------------------------ helpers ------------------------------------

__device__ __forceinline__ uint32_t smem_u32(const void* p) {
    uint32_t a;
    asm("{ .reg .u64 t; cvta.to.shared.u64 t, %1; cvt.u32.u64 %0, t; }"
        : "=r"(a) : "l"(p));
    return a;
}
__device__ __forceinline__ void cp16(uint32_t dst, const void* src) {
    asm volatile("cp.async.cg.shared.global [%0], [%1], 16;"
                 :: "r"(dst), "l"(src));
}
#define CP_COMMIT() asm volatile("cp.async.commit_group;" ::: "memory")
#define CP_WAIT1()  asm volatile("cp.async.wait_group 1;" ::: "memory")
#define CP_WAIT0()  asm volatile("cp.async.wait_group 0;" ::: "memory")

__device__ __forceinline__ void ldsm_x4(uint32_t addr, uint32_t* r) {
    asm volatile("ldmatrix.sync.aligned.m8n8.x4.shared.b16 {%0,%1,%2,%3}, [%4];"
                 : "=r"(r[0]), "=r"(r[1]), "=r"(r[2]), "=r"(r[3]) : "r"(addr));
}
__device__ __forceinline__ void ldsm_x4_t(uint32_t addr, uint32_t* r) {
    asm volatile("ldmatrix.sync.aligned.m8n8.x4.trans.shared.b16 {%0,%1,%2,%3}, [%4];"
                 : "=r"(r[0]), "=r"(r[1]), "=r"(r[2]), "=r"(r[3]) : "r"(addr));
}
__device__ __forceinline__ void mma16816(float* c, const uint32_t* a,
                                         const uint32_t* b) {
    asm volatile(
        "mma.sync.aligned.m16n8k16.row.col.f32.f16.f16.f32 "
        "{%0,%1,%2,%3}, {%4,%5,%6,%7}, {%8,%9}, {%0,%1,%2,%3};"
        : "+f"(c[0]), "+f"(c[1]), "+f"(c[2]), "+f"(c[3])
        : "r"(a[0]), "r"(a[1]), "r"(a[2]), "r"(a[3]), "r"(b[0]), "r"(b[1]));
}
__device__ __forceinline__ uint32_t pack_h2(float x, float y) {
    __half2 v = __halves2half2(__float2half_rn(x), __float2half_rn(y));
    return *(uint32_t*)&v;
}

// ------------------------------ merged prep ---------------------------------
// blocks [0, NB_X): x -> fp16;  [NB_X, NB_X+256): weights; rest: bias+mask.

#define NB_X ((M_ROWS * CH / 4) / 256)   // 50176

__global__ void k_prep(const float* __restrict__ x,
                       const float* __restrict__ wq,
                       const float* __restrict__ wk,
                       const float* __restrict__ wv,
                       const float* __restrict__ wo,
                       const float* __restrict__ mask,
                       const float* __restrict__ bias_table,
                       const int* __restrict__ rel_index)
{
    const int blk = blockIdx.x;
    if (blk < NB_X) {
        int i = blk * 256 + threadIdx.x;
        float4 v = ((const float4*)x)[i];
        ((__half2*)g_xh)[i * 2] =
            __halves2half2(__float2half_rn(v.x), __float2half_rn(v.y));
        ((__half2*)g_xh)[i * 2 + 1] =
            __halves2half2(__float2half_rn(v.z), __float2half_rn(v.w));
    } else if (blk < NB_X + 256) {
        int gid = (blk - NB_X) * 256 + threadIdx.x;
        int sect = gid >> 14;
        int i    = gid & 16383;
        const float* src = (sect == 0) ? wq : (sect == 1) ? wk
                         : (sect == 2) ? wv : wo;
        float4 v = ((const float4*)src)[i];
        __half2 a = __halves2half2(__float2half_rn(v.x), __float2half_rn(v.y));
        __half2 b = __halves2half2(__float2half_rn(v.z), __float2half_rn(v.w));
        int k = (i * 4) >> 8;
        int n = (i * 4) & 255;
        if (sect < 3) {
            __half2* d = (__half2*)&g_wqkv[(size_t)k * 768 + sect * 256 + n];
            d[0] = a; d[1] = b;
        } else {
            __half2* d = (__half2*)&g_wo[(size_t)k * 256 + n];
            d[0] = a; d[1] = b;
        }
    } else {
        const int bid = blk - (NB_X + 256);     // 0..511
        const int w   = bid >> 3;
        const int h   = bid & 7;
        float* dst = g_bm + (size_t)bid * BMWIN;
        const float* mrow = mask + (size_t)w * (L_TOK * L_TOK);
        for (int i = threadIdx.x; i < L_TOK * L_TOK; i += 256)
            dst[(i / L_TOK) * BMROW + (i % L_TOK)] =
                bias_table[rel_index[i] * NHEAD + h] + mrow[i];
    }
}

// ------------------------------ GEMM ----------------------------------------
// BM=128 BN=128 BK=64, 4 warps (2m x 2n), warp tile 64x64, 2-stage.

#define AROWH 72
#define BROWH 136
#define O_A 0
#define O_B 18432
#define S_BUF 35840
#define SMEM_BYTES (2 * S_BUF)
#define CS 136

__global__ __launch_bounds__(128, 2)
void k_hgemm(const __half* __restrict__ Ah, const __half* __restrict__ Wh,
             int ldW, float* __restrict__ Cf, int ldC, int mode)
{
    extern __shared__ char smem[];
    const uint32_t sb = smem_u32(smem);
    const int tid  = threadIdx.x;
    const int lane = tid & 31;
    const int wid  = tid >> 5;
    const int warp_m = wid & 1;
    const int warp_n = wid >> 1;
    const int rowBlock = blockIdx.y * 128;
    const int col0     = blockIdx.x * 128;

    float acc[4][8][4];
#pragma unroll
    for (int mt = 0; mt < 4; mt++)
#pragma unroll
        for (int nt = 0; nt < 8; nt++)
#pragma unroll
            for (int i = 0; i < 4; i++) acc[mt][nt][i] = 0.f;

    auto issue = [&](int c, int buf) {
        uint32_t s = sb + buf * S_BUF;
#pragma unroll
        for (int q8 = 0; q8 < 8; q8++) {
            int q   = tid + 128 * q8;
            int row = q >> 3;
            int seg = (q & 7) * 8;
            cp16(s + O_A + row * (AROWH * 2) + seg * 2,
                 Ah + (size_t)(rowBlock + row) * CH + c * 64 + seg);
        }
#pragma unroll
        for (int q8 = 0; q8 < 8; q8++) {
            int q   = tid + 128 * q8;
            int k   = q >> 4;
            int seg = (q & 15) * 8;
            cp16(s + O_B + k * (BROWH * 2) + seg * 2,
                 Wh + (size_t)(c * 64 + k) * ldW + col0 + seg);
        }
        CP_COMMIT();
    };

    const int arow_l = warp_m * 64 + (lane & 15);
    const int acol_l = (lane >> 4) * 8;
    const int brow_l = (lane & 7) + ((lane >> 3) & 1) * 8;
    const int bcol_l = warp_n * 64 + (lane >> 4) * 8;

    issue(0, 0);

#pragma unroll 1
    for (int c = 0; c < 4; c++) {
        if (c < 3) { issue(c + 1, (c + 1) & 1); CP_WAIT1(); }
        else       { CP_WAIT0(); }
        __syncthreads();

        const uint32_t s = sb + (c & 1) * S_BUF;
#pragma unroll
        for (int ks = 0; ks < 4; ks++) {
            uint32_t a[4][4], b[4][4];
            const uint32_t aoff = (acol_l + ks * 16) * 2;
#pragma unroll
            for (int mt = 0; mt < 4; mt++)
                ldsm_x4(s + O_A + (arow_l + mt * 16) * (AROWH * 2) + aoff,
                        a[mt]);
            const uint32_t brow = (brow_l + ks * 16) * (BROWH * 2);
#pragma unroll
            for (int np = 0; np < 4; np++)
                ldsm_x4_t(s + O_B + brow + (bcol_l + np * 16) * 2, b[np]);
#pragma unroll
            for (int mt = 0; mt < 4; mt++)
#pragma unroll
                for (int nt = 0; nt < 8; nt++)
                    mma16816(acc[mt][nt], a[mt], &b[nt >> 1][(nt & 1) * 2]);
        }
        __syncthreads();
    }

    // ---- epilogue via smem -> STG.128 ----
    float* cs = (float*)smem;
    const int g  = lane >> 2;
    const int tc = (lane & 3) * 2;
#pragma unroll
    for (int mt = 0; mt < 4; mt++) {
        const int r = warp_m * 64 + mt * 16 + g;
#pragma unroll
        for (int nt = 0; nt < 8; nt++) {
            const int cc = warp_n * 64 + nt * 8 + tc;
            *(float2*)&cs[r * CS + cc] =
                make_float2(acc[mt][nt][0], acc[mt][nt][1]);
            *(float2*)&cs[(r + 8) * CS + cc] =
                make_float2(acc[mt][nt][2], acc[mt][nt][3]);
        }
    }
    __syncthreads();

#pragma unroll
    for (int i = 0; i < 16; i++) {
        const int id  = tid + 128 * i;
        const int row = id >> 4;
        const int col = (id & 15) * 8;
        float4 v0 = *(float4*)&cs[row * CS + col];
        float4 v1 = *(float4*)&cs[row * CS + col + 4];
        if (mode == 0) {
            uint4 hi;
            hi.x = pack_h2(v0.x, v0.y); hi.y = pack_h2(v0.z, v0.w);
            hi.z = pack_h2(v1.x, v1.y); hi.w = pack_h2(v1.z, v1.w);
            size_t o = (size_t)(rowBlock + row) * 768 + col0 + col;
            *(uint4*)&g_qh[o] = hi;
        } else {
            size_t o = (size_t)(rowBlock + row) * ldC + col0 + col;
            *(float4*)&Cf[o]     = v0;
            *(float4*)&Cf[o + 4] = v1;
        }
    }
}

// ------------------------------ attention (HMMA) ----------------------------
// One CTA per (window, head), 4 warps. QK 1-pass, AV 1-pass, cp.async loads.

#define KSTR 40

__global__ __launch_bounds__(128)
void attn_kernel()
{
    __shared__ __align__(16) __half sQ [64 * KSTR];
    __shared__ __align__(16) __half sKh[64 * KSTR];
    __shared__ __align__(16) __half sVh[64 * KSTR];

    const int bid = blockIdx.x;
    const int h   = bid & 7;
    const int n   = bid >> 3;
    const int tid = threadIdx.x;

    // cp.async Q, K, V (hi planes): 3 planes x 49 rows x 4 x 16B
    {
        const size_t rb = (size_t)n * L_TOK * 768 + h * DK;
        const uint32_t q0 = smem_u32(sQ);
        const uint32_t k0 = smem_u32(sKh);
        const uint32_t v0 = smem_u32(sVh);
        for (int idx = tid; idx < 3 * 196; idx += 128) {
            int p   = idx / 196;
            int rem = idx - p * 196;
            int r   = rem >> 2;
            int q4  = rem & 3;
            const __half* src;
            uint32_t dst;
            switch (p) {
                case 0: src = g_qh + rb;       dst = q0; break;
                case 1: src = g_qh + rb + 256; dst = k0; break;
                default: src = g_qh + rb + 512; dst = v0; break;
            }
            cp16(dst + (r * KSTR + q4 * 8) * 2,
                 src + (size_t)r * 768 + q4 * 8);
        }
        CP_COMMIT();
    }
    // zero V pad rows 49..63 (plain STS, ordered by the barrier below)
    for (int idx = tid; idx < 60; idx += 128) {
        int r  = 49 + (idx >> 2);
        int q4 = idx & 3;
        *(int4*)(sVh + r * KSTR + q4 * 8) = make_int4(0, 0, 0, 0);
    }
    CP_WAIT0();
    __syncthreads();

    const int warp = tid >> 5;
    const int lane = tid & 31;
    const int g    = lane >> 2;
    const int t    = lane & 3;

    const uint32_t bq  = smem_u32(sQ);
    const uint32_t bkh = smem_u32(sKh);
    const int aRow = warp * 16 + (lane & 15);
    const int aCol = (lane >> 4) * 8;

    uint32_t qa[2][4];
    ldsm_x4(bq + (aRow * KSTR + aCol) * 2, qa[0]);
    ldsm_x4(bq + (aRow * KSTR + aCol + 16) * 2, qa[1]);

    float c[8][4];
#pragma unroll
    for (int nt = 0; nt < 8; nt++)
#pragma unroll
        for (int i = 0; i < 4; i++) c[nt][i] = 0.f;

#pragma unroll
    for (int kt = 0; kt < 2; kt++) {
#pragma unroll
        for (int jp = 0; jp < 4; jp++) {
            uint32_t kb[4];
            ldsm_x4(bkh + ((jp * 16 + (lane & 15)) * KSTR +
                           (lane >> 4) * 8 + kt * 16) * 2, kb);
            uint32_t b0[2] = {kb[0], kb[2]};
            uint32_t b1[2] = {kb[1], kb[3]};
            mma16816(c[jp * 2],     qa[kt], b0);
            mma16816(c[jp * 2 + 1], qa[kt], b1);
        }
    }

    // ---- bias+mask direct from L2, softmax ----
    const int r0 = warp * 16 + g;
    const int r1 = r0 + 8;
    const float* bm = g_bm + (size_t)(((n & 63) << 3) | h) * BMWIN;
    const int r0e = (r0 < L_TOK ? r0 : L_TOK - 1) * BMROW;
    const int r1e = (r1 < L_TOK ? r1 : L_TOK - 1) * BMROW;
#pragma unroll
    for (int nt = 0; nt < 8; nt++) {
        const int j0 = nt * 8 + t * 2;
        if (j0 < L_TOK) {
            float2 b0 = __ldg((const float2*)&bm[r0e + j0]);
            float2 b1 = __ldg((const float2*)&bm[r1e + j0]);
            c[nt][0] += b0.x;
            c[nt][2] += b1.x;
            if (j0 + 1 < L_TOK) { c[nt][1] += b0.y; c[nt][3] += b1.y; }
            else { c[nt][1] = -3.0e38f; c[nt][3] = -3.0e38f; }
        } else {
            c[nt][0] = c[nt][1] = c[nt][2] = c[nt][3] = -3.0e38f;
        }
    }

    float mx0 = -3.0e38f, mx1 = -3.0e38f;
#pragma unroll
    for (int nt = 0; nt < 8; nt++) {
        mx0 = fmaxf(mx0, fmaxf(c[nt][0], c[nt][1]));
        mx1 = fmaxf(mx1, fmaxf(c[nt][2], c[nt][3]));
    }
    mx0 = fmaxf(mx0, __shfl_xor_sync(0xffffffffu, mx0, 1));
    mx0 = fmaxf(mx0, __shfl_xor_sync(0xffffffffu, mx0, 2));
    mx1 = fmaxf(mx1, __shfl_xor_sync(0xffffffffu, mx1, 1));
    mx1 = fmaxf(mx1, __shfl_xor_sync(0xffffffffu, mx1, 2));

    float s0 = 0.f, s1 = 0.f;
#pragma unroll
    for (int nt = 0; nt < 8; nt++) {
        c[nt][0] = __expf(c[nt][0] - mx0); s0 += c[nt][0];
        c[nt][1] = __expf(c[nt][1] - mx0); s0 += c[nt][1];
        c[nt][2] = __expf(c[nt][2] - mx1); s1 += c[nt][2];
        c[nt][3] = __expf(c[nt][3] - mx1); s1 += c[nt][3];
    }
    s0 += __shfl_xor_sync(0xffffffffu, s0, 1);
    s0 += __shfl_xor_sync(0xffffffffu, s0, 2);
    s1 += __shfl_xor_sync(0xffffffffu, s1, 1);
    s1 += __shfl_xor_sync(0xffffffffu, s1, 2);
    const float rs0 = 1.f / s0;
    const float rs1 = 1.f / s1;

    // ---- AV: single pass ----
    const uint32_t bvh = smem_u32(sVh);
    const int vRow = (lane & 7) + ((lane >> 3) & 1) * 8;
    const int vCol = (lane >> 4) * 8;

    float o[4][4];
#pragma unroll
    for (int nt = 0; nt < 4; nt++)
#pragma unroll
        for (int i = 0; i < 4; i++) o[nt][i] = 0.f;

#pragma unroll
    for (int kt = 0; kt < 4; kt++) {
        uint32_t ph[4];
#pragma unroll
        for (int q = 0; q < 2; q++) {
            const float* cc = c[2 * kt + q];
            ph[q * 2]     = pack_h2(cc[0], cc[1]);
            ph[q * 2 + 1] = pack_h2(cc[2], cc[3]);
        }
        uint32_t vh[2][4];
        const uint32_t roff = (kt * 16 + vRow) * KSTR;
        ldsm_x4_t(bvh + (roff + vCol) * 2,      vh[0]);
        ldsm_x4_t(bvh + (roff + vCol + 16) * 2, vh[1]);
#pragma unroll
        for (int nt = 0; nt < 4; nt++)
            mma16816(o[nt], ph, &vh[nt >> 1][(nt & 1) * 2]);
    }

    if (r0 < L_TOK) {
        __half* orow = g_ah + (size_t)(n * L_TOK + r0) * CH + h * DK;
#pragma unroll
        for (int nt = 0; nt < 4; nt++)
            *(__half2*)&orow[nt * 8 + t * 2] =
                __halves2half2(__float2half_rn(o[nt][0] * rs0),
                               __float2half_rn(o[nt][1] * rs0));
    }
    if (r1 < L_TOK) {
        __half* orow = g_ah + (size_t)(n * L_TOK + r1) * CH + h * DK;
#pragma unroll
        for (int nt = 0; nt < 4; nt++)
            *(__half2*)&orow[nt * 8 + t * 2] =
                __halves2half2(__float2half_rn(o[nt][2] * rs1),
                               __float2half_rn(o[nt][3] * rs1));
    }
}

// ------------------------------- launch --------------------------------------

extern "C" void kernel_launch(void* const* d_in, const int* in_sizes, int n_in,
                              void* d_out, int out_size)
{
    (void)in_sizes; (void)n_in; (void)out_size;
    const float* x    = (const float*)d_in[0];
    const float* mask = (const float*)d_in[1];
    const float* wq   = (const float*)d_in[2];
    const float* wk   = (const float*)d_in[3];
    const float* wv   = (const float*)d_in[4];
    const float* wo   = (const float*)d_in[5];
    const float* bias = (const float*)d_in[6];
    const int*   rel  = (const int*)d_in[7];
    float* out = (float*)d_out;

    static __half *xh = nullptr, *ah = nullptr, *wqkv = nullptr, *woh = nullptr;
    if (!xh) {
        cudaGetSymbolAddress((void**)&xh,   g_xh);
        cudaGetSymbolAddress((void**)&ah,   g_ah);
        cudaGetSymbolAddress((void**)&wqkv, g_wqkv);
        cudaGetSymbolAddress((void**)&woh,  g_wo);
        cudaFuncSetAttribute(k_hgemm,
                             cudaFuncAttributeMaxDynamicSharedMemorySize,
                             SMEM_BYTES);
    }

    k_prep<<<NB_X + 256 + 512, 256>>>(x, wq, wk, wv, wo, mask, bias, rel);
    k_hgemm<<<dim3(6, M_ROWS / 128), 128, SMEM_BYTES>>>(xh, wqkv, 768,
                                                        nullptr, 768, 0);
    attn_kernel<<<N_WIN * NHEAD, 128>>>();
    k_hgemm<<<dim3(2, M_ROWS / 128), 128, SMEM_BYTES>>>(ah, woh, 256,
                                                        out, 256, 1);
}